// round 9
// baseline (speedup 1.0000x reference)
#include <cuda_runtime.h>
#include <cstdint>

// Entmax (alpha=1.5) per row, B=2048 x N=32000 fp32.
// v8: persistent CTA + split-row TMA prefetch.
//   Row = part1 (24000 fl, P1a/P1b ping-pong) + part2 (8000 fl, P2).
//   part1(row+2) is issued right after copy(row): a TMA is ALWAYS in flight,
//   so the DRAM read stream has no per-row hole. Row processed register-
//   resident: filter@rowmax-1 -> warp-0 Newton -> stcs output.

#define NC        32000
#define N1        24000          // part1 floats
#define N2        8000           // part2 floats
#define NV1       (N1 / 4)       // 6000 float4
#define NV2       (N2 / 4)       // 2000 float4
#define TPB       1024
#define VP1       6              // float4 slots for part1 (6*1024 >= 6000)
#define VP2       2              // float4 slots for part2 (2*1024 >= 2000)
#define VPT       (VP1 + VP2)
#define CAP       512
#define NEG       (-1e30f)
#define P1_BYTES  (N1 * 4)       // 96000
#define P2_BYTES  (N2 * 4)       // 32000

__device__ __forceinline__ uint32_t smem_u32(const void* p) {
    uint32_t a;
    asm("{ .reg .u64 t; cvta.to.shared.u64 t, %1; cvt.u32.u64 %0, t; }"
        : "=r"(a) : "l"(p));
    return a;
}
__device__ __forceinline__ void mbar_init(uint32_t a, uint32_t cnt) {
    asm volatile("mbarrier.init.shared.b64 [%0], %1;" :: "r"(a), "r"(cnt) : "memory");
}
__device__ __forceinline__ void mbar_expect_tx(uint32_t a, uint32_t bytes) {
    asm volatile("mbarrier.arrive.expect_tx.shared.b64 _, [%0], %1;"
                 :: "r"(a), "r"(bytes) : "memory");
}
__device__ __forceinline__ void tma_bulk_g2s(uint32_t dst, const void* src,
                                             uint32_t bytes, uint32_t mbar) {
    asm volatile(
        "cp.async.bulk.shared::cta.global.mbarrier::complete_tx::bytes "
        "[%0], [%1], %2, [%3];"
        :: "r"(dst), "l"(src), "r"(bytes), "r"(mbar) : "memory");
}
#define MBAR_WAIT(mbar, parity) do { \
    asm volatile( \
        "{\n\t.reg .pred P1;\n\t" \
        "WAIT_LOOP_%=:\n\t" \
        "mbarrier.try_wait.parity.acquire.cta.shared::cta.b64 P1, [%0], %1, 0x989680;\n\t" \
        "@P1 bra.uni WAIT_DONE_%=;\n\t" \
        "bra.uni WAIT_LOOP_%=;\n\t" \
        "WAIT_DONE_%=:\n\t}" \
        :: "r"(mbar), "r"(parity) : "memory"); \
} while (0)

__global__ __launch_bounds__(TPB, 1)
void entmax_kernel(const float* __restrict__ z, float* __restrict__ out,
                   int rows, int gstride) {
    __shared__ float    s_f[32];      // max partials
    __shared__ float    s_g[32];      // vmax partials
    __shared__ int      s_i[32];      // fallback count partials
    __shared__ float    s_h[32];      // fallback sum partials
    __shared__ float    s_cand[CAP];
    __shared__ int      s_cnt;
    __shared__ float    s_tauref;
    __shared__ int      s_bK;
    __shared__ float    s_bS, s_bV;
    __shared__ uint64_t s_mb1[2];     // for P1a / P1b
    __shared__ uint64_t s_mb2;        // for P2
    extern __shared__ float4 s_dyn[]; // [P1a NV1][P1b NV1][P2 NV2] = 218.75 KB

    const int tid  = threadIdx.x;
    const int lane = tid & 31;
    const int wid  = tid >> 5;

    const uint32_t mb1[2] = { smem_u32(&s_mb1[0]), smem_u32(&s_mb1[1]) };
    const uint32_t mb2    = smem_u32(&s_mb2);
    float4* const p1buf[2] = { s_dyn, s_dyn + NV1 };
    float4* const p2buf    = s_dyn + 2 * NV1;
    const uint32_t p1a[2]  = { smem_u32(p1buf[0]), smem_u32(p1buf[1]) };
    const uint32_t p2a     = smem_u32(p2buf);

    if (tid == 0) {
        mbar_init(mb1[0], 1);
        mbar_init(mb1[1], 1);
        mbar_init(mb2, 1);
    }
    __syncthreads();

    const int r0     = blockIdx.x;
    const int myrows = (r0 < rows) ? ((rows - r0 - 1) / gstride + 1) : 0;

    // prologue: part1(row0)->P1a, part2(row0)->P2, part1(row1)->P1b
    if (tid == 0 && myrows > 0) {
        const float* row0 = z + (long long)r0 * NC;
        mbar_expect_tx(mb1[0], P1_BYTES);
        tma_bulk_g2s(p1a[0], row0, P1_BYTES, mb1[0]);
        mbar_expect_tx(mb2, P2_BYTES);
        tma_bulk_g2s(p2a, row0 + N1, P2_BYTES, mb2);
        if (myrows > 1) {
            const float* row1 = z + (long long)(r0 + gstride) * NC;
            mbar_expect_tx(mb1[1], P1_BYTES);
            tma_bulk_g2s(p1a[1], row1, P1_BYTES, mb1[1]);
        }
    }

    for (int ri = 0; ri < myrows; ++ri) {
        const int row = r0 + ri * gstride;
        const int b   = ri & 1;                       // P1 buffer for this row

        // ---- wait for this row's two parts; copy -> regs fused with max ----
        MBAR_WAIT(mb1[b], (uint32_t)((ri >> 1) & 1));
        MBAR_WAIT(mb2,    (uint32_t)(ri & 1));

        float4 r[VPT];
        float lmax = NEG;
        const float4* bp1 = p1buf[b];
        #pragma unroll
        for (int j = 0; j < VP1; ++j) {
            const int f = tid + j * TPB;
            if (f < NV1) {
                float4 v = bp1[f];
                r[j] = v;
                lmax = fmaxf(lmax, fmaxf(fmaxf(v.x, v.y), fmaxf(v.z, v.w)));
            } else {
                r[j] = make_float4(NEG, NEG, NEG, NEG);
            }
        }
        #pragma unroll
        for (int j = 0; j < VP2; ++j) {
            const int f = tid + j * TPB;
            if (f < NV2) {
                float4 v = p2buf[f];
                r[VP1 + j] = v;
                lmax = fmaxf(lmax, fmaxf(fmaxf(v.x, v.y), fmaxf(v.z, v.w)));
            } else {
                r[VP1 + j] = make_float4(NEG, NEG, NEG, NEG);
            }
        }
        __syncthreads();               // (1) buffer reads done

        // ---- re-arm: part2(row+1) -> P2, part1(row+2) -> this P1 buffer ----
        if (tid == 0) {
            asm volatile("fence.proxy.async.shared::cta;" ::: "memory");
            if (ri + 1 < myrows) {
                const float* nrow = z + (long long)(row + gstride) * NC;
                mbar_expect_tx(mb2, P2_BYTES);
                tma_bulk_g2s(p2a, nrow + N1, P2_BYTES, mb2);
            }
            if (ri + 2 < myrows) {
                const float* nnrow = z + (long long)(row + 2 * gstride) * NC;
                mbar_expect_tx(mb1[b], P1_BYTES);
                tma_bulk_g2s(p1a[b], nnrow, P1_BYTES, mb1[b]);
            }
            s_cnt = 0;
        }

        // ---- max reduce: partials published once, every warp finishes ----
        #pragma unroll
        for (int o = 16; o; o >>= 1)
            lmax = fmaxf(lmax, __shfl_xor_sync(0xffffffffu, lmax, o));
        if (lane == 0) s_f[wid] = lmax;
        __syncthreads();               // (2) partials + s_cnt=0 visible
        float m = s_f[lane];
        #pragma unroll
        for (int o = 16; o; o >>= 1)
            m = fmaxf(m, __shfl_xor_sync(0xffffffffu, m, o));
        const float tau0 = m - 1.0f;

        // ---- filter: candidates z > tau0 (tau0 <= tau*: support-complete) --
        float vmax = NEG;
        #pragma unroll
        for (int j = 0; j < VPT; ++j) {
            float c;
            c = r[j].x; if (c > tau0) { int p = atomicAdd(&s_cnt, 1); if (p < CAP) s_cand[p] = c; } else vmax = fmaxf(vmax, c);
            c = r[j].y; if (c > tau0) { int p = atomicAdd(&s_cnt, 1); if (p < CAP) s_cand[p] = c; } else vmax = fmaxf(vmax, c);
            c = r[j].z; if (c > tau0) { int p = atomicAdd(&s_cnt, 1); if (p < CAP) s_cand[p] = c; } else vmax = fmaxf(vmax, c);
            c = r[j].w; if (c > tau0) { int p = atomicAdd(&s_cnt, 1); if (p < CAP) s_cand[p] = c; } else vmax = fmaxf(vmax, c);
        }
        #pragma unroll
        for (int o = 16; o; o >>= 1)
            vmax = fmaxf(vmax, __shfl_xor_sync(0xffffffffu, vmax, o));
        if (lane == 0) s_g[wid] = vmax;
        __syncthreads();               // (3) cand/cnt/vmax visible
        const int cnt = s_cnt;
        float tau_ref;

        if (cnt <= CAP) {
            // ---- warp 0: private vmax reduce + Newton on candidates ----
            if (wid == 0) {
                float gv = s_g[lane];
                #pragma unroll
                for (int o = 16; o; o >>= 1)
                    gv = fmaxf(gv, __shfl_xor_sync(0xffffffffu, gv, o));

                float tl = tau0;
                int   kp = -1;
                int   kF = 1; float SF = 0.0f; float vcF = NEG;
                for (int itr = 0; itr < 64; ++itr) {
                    int k = 0; float S = 0.0f; float vc = NEG;
                    for (int i = lane; i < cnt; i += 32) {
                        const float c = s_cand[i];
                        if (c > tl) { k++; S += c; } else vc = fmaxf(vc, c);
                    }
                    #pragma unroll
                    for (int o = 16; o; o >>= 1) {
                        k += __shfl_xor_sync(0xffffffffu, k, o);
                        S += __shfl_xor_sync(0xffffffffu, S, o);
                        vc = fmaxf(vc, __shfl_xor_sync(0xffffffffu, vc, o));
                    }
                    kF = k; SF = S; vcF = vc;
                    if (k == kp) break;           // support fixed point
                    kp = k;
                    tl = (S - 1.0f) / (float)k;
                }
                // reference quirk: cs[k_max] = S + max{z <= tau_final}
                const float vfin = fmaxf(vcF, gv);
                const float vt = (vfin > -1e29f) ? vfin : 0.0f;
                if (lane == 0) s_tauref = (SF + vt - 1.0f) / (float)kF;
            }
            __syncthreads();           // (4) tau_ref published
            tau_ref = s_tauref;
        } else {
            // ---- fallback: block-wide Newton over register data ----
            float tau = tau0;
            int kprev = -1;
            tau_ref = 0.0f;
            for (int it = 0; it < 64; ++it) {
                int k = 0; float S = 0.0f; float v = NEG;
                #pragma unroll
                for (int j = 0; j < VPT; ++j) {
                    float c;
                    c = r[j].x; if (c > tau) { k++; S += c; } else v = fmaxf(v, c);
                    c = r[j].y; if (c > tau) { k++; S += c; } else v = fmaxf(v, c);
                    c = r[j].z; if (c > tau) { k++; S += c; } else v = fmaxf(v, c);
                    c = r[j].w; if (c > tau) { k++; S += c; } else v = fmaxf(v, c);
                }
                #pragma unroll
                for (int o = 16; o; o >>= 1) {
                    k += __shfl_xor_sync(0xffffffffu, k, o);
                    S += __shfl_xor_sync(0xffffffffu, S, o);
                    v  = fmaxf(v, __shfl_xor_sync(0xffffffffu, v, o));
                }
                if (lane == 0) { s_i[wid] = k; s_h[wid] = S; s_g[wid] = v; }
                __syncthreads();
                if (tid < 32) {
                    int kk = s_i[tid]; float SS = s_h[tid]; float vv = s_g[tid];
                    #pragma unroll
                    for (int o = 16; o; o >>= 1) {
                        kk += __shfl_xor_sync(0xffffffffu, kk, o);
                        SS += __shfl_xor_sync(0xffffffffu, SS, o);
                        vv  = fmaxf(vv, __shfl_xor_sync(0xffffffffu, vv, o));
                    }
                    if (tid == 0) { s_bK = kk; s_bS = SS; s_bV = vv; }
                }
                __syncthreads();
                const int   K  = s_bK;
                const float Sa = s_bS;
                const float Va = s_bV;
                if (K == kprev || it == 63) {
                    const float vt = (Va > -1e29f) ? Va : 0.0f;
                    tau_ref = (Sa + vt - 1.0f) / (float)K;
                    break;
                }
                kprev = K;
                tau = (Sa - 1.0f) / (float)K;
                __syncthreads();
            }
        }

        // ---- output: relu(z - tau_ref)^1.5 from registers ----
        float* orow = out + (long long)row * NC;
        float4* o1 = (float4*)orow;            // part1 region
        float4* o2 = (float4*)(orow + N1);     // part2 region
        #pragma unroll
        for (int j = 0; j < VP1; ++j) {
            const int f = tid + j * TPB;
            if (f < NV1) {
                const float4 v = r[j];
                float a = v.x - tau_ref, bb = v.y - tau_ref;
                float c = v.z - tau_ref, d = v.w - tau_ref;
                float4 o;
                if (fmaxf(fmaxf(a, bb), fmaxf(c, d)) > 0.0f) {
                    a = fmaxf(a, 0.0f); bb = fmaxf(bb, 0.0f);
                    c = fmaxf(c, 0.0f); d = fmaxf(d, 0.0f);
                    o.x = a * sqrtf(a);  o.y = bb * sqrtf(bb);
                    o.z = c * sqrtf(c);  o.w = d * sqrtf(d);
                } else {
                    o.x = 0.0f; o.y = 0.0f; o.z = 0.0f; o.w = 0.0f;
                }
                __stcs(&o1[f], o);
            }
        }
        #pragma unroll
        for (int j = 0; j < VP2; ++j) {
            const int f = tid + j * TPB;
            if (f < NV2) {
                const float4 v = r[VP1 + j];
                float a = v.x - tau_ref, bb = v.y - tau_ref;
                float c = v.z - tau_ref, d = v.w - tau_ref;
                float4 o;
                if (fmaxf(fmaxf(a, bb), fmaxf(c, d)) > 0.0f) {
                    a = fmaxf(a, 0.0f); bb = fmaxf(bb, 0.0f);
                    c = fmaxf(c, 0.0f); d = fmaxf(d, 0.0f);
                    o.x = a * sqrtf(a);  o.y = bb * sqrtf(bb);
                    o.z = c * sqrtf(c);  o.w = d * sqrtf(d);
                } else {
                    o.x = 0.0f; o.y = 0.0f; o.z = 0.0f; o.w = 0.0f;
                }
                __stcs(&o2[f], o);
            }
        }
    }
}

extern "C" void kernel_launch(void* const* d_in, const int* in_sizes, int n_in,
                              void* d_out, int out_size) {
    const float* z = (const float*)d_in[0];
    float* out = (float*)d_out;
    const int rows = in_sizes[0] / NC;

    int dev = 0, sms = 148;
    cudaGetDevice(&dev);
    cudaDeviceGetAttribute(&sms, cudaDevAttrMultiProcessorCount, dev);

    const int dyn_bytes = 2 * P1_BYTES + P2_BYTES;   // 224000 B
    cudaFuncSetAttribute(entmax_kernel,
                         cudaFuncAttributeMaxDynamicSharedMemorySize, dyn_bytes);

    const int grid = (rows < sms) ? rows : sms;
    entmax_kernel<<<grid, TPB, dyn_bytes>>>(z, out, rows, grid);
}

// round 10
// speedup vs baseline: 1.2355x; 1.2355x over previous
#include <cuda_runtime.h>
#include <cstdint>

// Entmax (alpha=1.5) per row, B=2048 x N=32000 fp32.
// v9 = v7 core + in-place half-row TMA double-buffering:
//   single 125 KB smem buffer (keeps L1 carveout big -- the v6/v8 lesson),
//   but each half is re-armed with the NEXT row's data right after its copy,
//   so ~64-128 KB of TMA read is in flight through the whole row period.
//   TMA issued as 4x16000B chunks per half for engine MLP.
//   Filter sweep cut to ~5 ALU ops / float4 via max-tree pre-test.

#define NC        32000
#define NV        (NC / 4)       // 8000 float4
#define NVH_      4000           // float4 per half
#define TPB       1024
#define VPT       8
#define VPH       4              // slots per half (4*1024 >= 4000)
#define CAP       1024
#define NEG       (-1e30f)
#define HALF_BYTES 64000
#define CHUNKS    4
#define CHUNK_B   (HALF_BYTES / CHUNKS)   // 16000

__device__ __forceinline__ uint32_t smem_u32(const void* p) {
    uint32_t a;
    asm("{ .reg .u64 t; cvta.to.shared.u64 t, %1; cvt.u32.u64 %0, t; }"
        : "=r"(a) : "l"(p));
    return a;
}
__device__ __forceinline__ void mbar_init(uint32_t a, uint32_t cnt) {
    asm volatile("mbarrier.init.shared.b64 [%0], %1;" :: "r"(a), "r"(cnt) : "memory");
}
__device__ __forceinline__ void mbar_expect_tx(uint32_t a, uint32_t bytes) {
    asm volatile("mbarrier.arrive.expect_tx.shared.b64 _, [%0], %1;"
                 :: "r"(a), "r"(bytes) : "memory");
}
__device__ __forceinline__ void tma_bulk_g2s(uint32_t dst, const void* src,
                                             uint32_t bytes, uint32_t mbar) {
    asm volatile(
        "cp.async.bulk.shared::cta.global.mbarrier::complete_tx::bytes "
        "[%0], [%1], %2, [%3];"
        :: "r"(dst), "l"(src), "r"(bytes), "r"(mbar) : "memory");
}
#define MBAR_WAIT(mbar, parity) do { \
    asm volatile( \
        "{\n\t.reg .pred P1;\n\t" \
        "WAIT_LOOP_%=:\n\t" \
        "mbarrier.try_wait.parity.acquire.cta.shared::cta.b64 P1, [%0], %1, 0x989680;\n\t" \
        "@P1 bra.uni WAIT_DONE_%=;\n\t" \
        "bra.uni WAIT_LOOP_%=;\n\t" \
        "WAIT_DONE_%=:\n\t}" \
        :: "r"(mbar), "r"(parity) : "memory"); \
} while (0)

// arm one half (4 chunked bulk copies, one expect_tx)
__device__ __forceinline__ void arm_half(uint32_t mbar, uint32_t dst_base,
                                         const float* src_base) {
    mbar_expect_tx(mbar, HALF_BYTES);
    #pragma unroll
    for (int c = 0; c < CHUNKS; ++c) {
        tma_bulk_g2s(dst_base + c * CHUNK_B,
                     src_base + c * (CHUNK_B / 4), CHUNK_B, mbar);
    }
}

__global__ __launch_bounds__(TPB, 1)
void entmax_kernel(const float* __restrict__ z, float* __restrict__ out,
                   int rows, int gstride) {
    __shared__ float    s_f[32];      // max partials
    __shared__ float    s_g[32];      // vmax partials
    __shared__ int      s_i[32];      // fallback count partials
    __shared__ float    s_h[32];      // fallback sum partials
    __shared__ float    s_cand[CAP];
    __shared__ int      s_cnt;
    __shared__ float    s_tauref;
    __shared__ int      s_bK;
    __shared__ float    s_bS, s_bV;
    __shared__ uint64_t s_mb[2];      // lower / upper half barriers
    extern __shared__ float4 s_buf[]; // NV float4 = 125 KB (single buffer)

    const int tid  = threadIdx.x;
    const int lane = tid & 31;
    const int wid  = tid >> 5;

    const uint32_t mbL = smem_u32(&s_mb[0]);
    const uint32_t mbH = smem_u32(&s_mb[1]);
    const uint32_t bufL = smem_u32(s_buf);
    const uint32_t bufH = bufL + HALF_BYTES;

    if (tid == 0) { mbar_init(mbL, 1); mbar_init(mbH, 1); }
    __syncthreads();

    const int r0     = blockIdx.x;
    const int myrows = (r0 < rows) ? ((rows - r0 - 1) / gstride + 1) : 0;

    if (tid == 0 && myrows > 0) {
        const float* row0 = z + (long long)r0 * NC;
        arm_half(mbL, bufL, row0);
        arm_half(mbH, bufH, row0 + 4 * NVH_);
    }

    for (int ri = 0; ri < myrows; ++ri) {
        const int row = r0 + ri * gstride;
        const uint32_t par = (uint32_t)(ri & 1);
        const float* nrow = z + (long long)(row + gstride) * NC;
        const bool have_next = (ri + 1 < myrows);

        float4 r[VPT];
        float lmax = NEG;

        // ---- lower half: wait, copy (fused max), re-arm for next row ----
        MBAR_WAIT(mbL, par);
        #pragma unroll
        for (int j = 0; j < VPH; ++j) {
            const int f = tid + j * TPB;
            if (f < NVH_) {
                float4 v = s_buf[f];
                r[j] = v;
                lmax = fmaxf(lmax, fmaxf(fmaxf(v.x, v.y), fmaxf(v.z, v.w)));
            } else {
                r[j] = make_float4(NEG, NEG, NEG, NEG);
            }
        }
        __syncthreads();                   // lower-half reads done
        if (tid == 0) {
            asm volatile("fence.proxy.async.shared::cta;" ::: "memory");
            if (have_next) arm_half(mbL, bufL, nrow);
        }

        // ---- upper half: wait, copy (fused max), re-arm for next row ----
        MBAR_WAIT(mbH, par);
        #pragma unroll
        for (int j = 0; j < VPH; ++j) {
            const int f = tid + j * TPB;
            if (f < NVH_) {
                float4 v = s_buf[NVH_ + f];
                r[VPH + j] = v;
                lmax = fmaxf(lmax, fmaxf(fmaxf(v.x, v.y), fmaxf(v.z, v.w)));
            } else {
                r[VPH + j] = make_float4(NEG, NEG, NEG, NEG);
            }
        }
        __syncthreads();                   // upper-half reads done
        if (tid == 0) {
            asm volatile("fence.proxy.async.shared::cta;" ::: "memory");
            if (have_next) arm_half(mbH, bufH, nrow + 4 * NVH_);
            s_cnt = 0;
        }

        // ---- max reduce: publish once; every warp finishes privately ----
        #pragma unroll
        for (int o = 16; o; o >>= 1)
            lmax = fmaxf(lmax, __shfl_xor_sync(0xffffffffu, lmax, o));
        if (lane == 0) s_f[wid] = lmax;
        __syncthreads();                   // partials + s_cnt=0 visible
        float m = s_f[lane];
        #pragma unroll
        for (int o = 16; o; o >>= 1)
            m = fmaxf(m, __shfl_xor_sync(0xffffffffu, m, o));
        const float tau0 = m - 1.0f;

        // ---- filter via max-tree pre-test (~5 ops / float4) ----
        float vmax = NEG;
        #pragma unroll
        for (int j = 0; j < VPT; ++j) {
            const float4 v = r[j];
            const float m4 = fmaxf(fmaxf(v.x, v.y), fmaxf(v.z, v.w));
            if (m4 > tau0) {               // rare path: inspect lanes
                float c;
                c = v.x; if (c > tau0) { int p = atomicAdd(&s_cnt, 1); if (p < CAP) s_cand[p] = c; } else vmax = fmaxf(vmax, c);
                c = v.y; if (c > tau0) { int p = atomicAdd(&s_cnt, 1); if (p < CAP) s_cand[p] = c; } else vmax = fmaxf(vmax, c);
                c = v.z; if (c > tau0) { int p = atomicAdd(&s_cnt, 1); if (p < CAP) s_cand[p] = c; } else vmax = fmaxf(vmax, c);
                c = v.w; if (c > tau0) { int p = atomicAdd(&s_cnt, 1); if (p < CAP) s_cand[p] = c; } else vmax = fmaxf(vmax, c);
            } else {
                vmax = fmaxf(vmax, m4);    // reject-max for free
            }
        }
        #pragma unroll
        for (int o = 16; o; o >>= 1)
            vmax = fmaxf(vmax, __shfl_xor_sync(0xffffffffu, vmax, o));
        if (lane == 0) s_g[wid] = vmax;
        __syncthreads();                   // cand/cnt/vmax visible
        const int cnt = s_cnt;
        float tau_ref;

        if (cnt <= CAP) {
            // ---- warp 0: private vmax reduce + Newton on candidates ----
            if (wid == 0) {
                float gv = s_g[lane];
                #pragma unroll
                for (int o = 16; o; o >>= 1)
                    gv = fmaxf(gv, __shfl_xor_sync(0xffffffffu, gv, o));

                float tl = tau0;
                int   kp = -1;
                int   kF = 1; float SF = 0.0f; float vcF = NEG;
                for (int itr = 0; itr < 64; ++itr) {
                    int k = 0; float S = 0.0f; float vc = NEG;
                    for (int i = lane; i < cnt; i += 32) {
                        const float c = s_cand[i];
                        if (c > tl) { k++; S += c; } else vc = fmaxf(vc, c);
                    }
                    #pragma unroll
                    for (int o = 16; o; o >>= 1) {
                        k += __shfl_xor_sync(0xffffffffu, k, o);
                        S += __shfl_xor_sync(0xffffffffu, S, o);
                        vc = fmaxf(vc, __shfl_xor_sync(0xffffffffu, vc, o));
                    }
                    kF = k; SF = S; vcF = vc;
                    if (k == kp) break;    // support fixed point
                    kp = k;
                    tl = (S - 1.0f) / (float)k;
                }
                // reference quirk: cs[k_max] = S + max{z <= tau_final}
                const float vfin = fmaxf(vcF, gv);
                const float vt = (vfin > -1e29f) ? vfin : 0.0f;
                if (lane == 0) s_tauref = (SF + vt - 1.0f) / (float)kF;
            }
            __syncthreads();               // tau_ref published
            tau_ref = s_tauref;
        } else {
            // ---- fallback: block-wide Newton over register data ----
            float tau = tau0;
            int kprev = -1;
            tau_ref = 0.0f;
            for (int it = 0; it < 64; ++it) {
                int k = 0; float S = 0.0f; float v = NEG;
                #pragma unroll
                for (int j = 0; j < VPT; ++j) {
                    float c;
                    c = r[j].x; if (c > tau) { k++; S += c; } else v = fmaxf(v, c);
                    c = r[j].y; if (c > tau) { k++; S += c; } else v = fmaxf(v, c);
                    c = r[j].z; if (c > tau) { k++; S += c; } else v = fmaxf(v, c);
                    c = r[j].w; if (c > tau) { k++; S += c; } else v = fmaxf(v, c);
                }
                #pragma unroll
                for (int o = 16; o; o >>= 1) {
                    k += __shfl_xor_sync(0xffffffffu, k, o);
                    S += __shfl_xor_sync(0xffffffffu, S, o);
                    v  = fmaxf(v, __shfl_xor_sync(0xffffffffu, v, o));
                }
                if (lane == 0) { s_i[wid] = k; s_h[wid] = S; s_g[wid] = v; }
                __syncthreads();
                if (tid < 32) {
                    int kk = s_i[tid]; float SS = s_h[tid]; float vv = s_g[tid];
                    #pragma unroll
                    for (int o = 16; o; o >>= 1) {
                        kk += __shfl_xor_sync(0xffffffffu, kk, o);
                        SS += __shfl_xor_sync(0xffffffffu, SS, o);
                        vv  = fmaxf(vv, __shfl_xor_sync(0xffffffffu, vv, o));
                    }
                    if (tid == 0) { s_bK = kk; s_bS = SS; s_bV = vv; }
                }
                __syncthreads();
                const int   K  = s_bK;
                const float Sa = s_bS;
                const float Va = s_bV;
                if (K == kprev || it == 63) {
                    const float vt = (Va > -1e29f) ? Va : 0.0f;
                    tau_ref = (Sa + vt - 1.0f) / (float)K;
                    break;
                }
                kprev = K;
                tau = (Sa - 1.0f) / (float)K;
                __syncthreads();
            }
        }

        // ---- output: relu(z - tau_ref)^1.5 from registers ----
        float4* orow = (float4*)(out + (long long)row * NC);
        #pragma unroll
        for (int h = 0; h < 2; ++h) {
            #pragma unroll
            for (int j = 0; j < VPH; ++j) {
                const int f = tid + j * TPB;
                if (f < NVH_) {
                    const float4 v = r[h * VPH + j];
                    float a = v.x - tau_ref, bb = v.y - tau_ref;
                    float c = v.z - tau_ref, d = v.w - tau_ref;
                    float4 o;
                    if (fmaxf(fmaxf(a, bb), fmaxf(c, d)) > 0.0f) {
                        a = fmaxf(a, 0.0f); bb = fmaxf(bb, 0.0f);
                        c = fmaxf(c, 0.0f); d = fmaxf(d, 0.0f);
                        o.x = a * sqrtf(a);  o.y = bb * sqrtf(bb);
                        o.z = c * sqrtf(c);  o.w = d * sqrtf(d);
                    } else {
                        o.x = 0.0f; o.y = 0.0f; o.z = 0.0f; o.w = 0.0f;
                    }
                    __stcs(&orow[h * NVH_ + f], o);
                }
            }
        }
    }
}

extern "C" void kernel_launch(void* const* d_in, const int* in_sizes, int n_in,
                              void* d_out, int out_size) {
    const float* z = (const float*)d_in[0];
    float* out = (float*)d_out;
    const int rows = in_sizes[0] / NC;

    int dev = 0, sms = 148;
    cudaGetDevice(&dev);
    cudaDeviceGetAttribute(&sms, cudaDevAttrMultiProcessorCount, dev);
    cudaFuncSetAttribute(entmax_kernel,
                         cudaFuncAttributeMaxDynamicSharedMemorySize, NV * 16);

    const int grid = (rows < sms) ? rows : sms;
    entmax_kernel<<<grid, TPB, NV * 16>>>(z, out, rows, grid);
}